// round 15
// baseline (speedup 1.0000x reference)
#include <cuda_runtime.h>
#include <cuda_fp16.h>
#include <math.h>
#include <stdint.h>

#define NN   8192
#define DIN  128
#define DH   48
#define DH1  256
#define DH2  128
#define DOUT 32

#define KSPLIT  4
#define TTILES  32            // j-tiles of 64 per K-quarter

typedef unsigned int u32;
typedef unsigned long long ull;

// ------------------------- scratch (device globals; no allocs) -------------
__device__ float g_Wh[NN * DH];
__device__ float g_s[NN];
__device__ float g_ea[NN];
__device__ float g_eb[NN];
__device__ __align__(16) u32 g_Bsw[128 * 2048];  // per-tile swizzled B fp16 (1 MB)
__device__ float g_part[256 * 128 * 64];         // per-CTA partial D (Z at col 48)
__device__ int   g_cnt[64];                      // per-i-tile completion counters
__device__ float g_hn[NN * DH];
__device__ float g_m1[NN * DH1];
__device__ float g_m2[NN * DH2];

// ------------------------- PTX helpers -------------------------------------
__device__ __forceinline__ void cpa16(void* dst_smem, const void* src) {
    u32 d = (u32)__cvta_generic_to_shared(dst_smem);
    asm volatile("cp.async.cg.shared.global [%0], [%1], 16;" :: "r"(d), "l"(src));
}
__device__ __forceinline__ void cpa_commit() {
    asm volatile("cp.async.commit_group;" ::: "memory");
}
__device__ __forceinline__ void cpa_wait0() {
    asm volatile("cp.async.wait_group 0;" ::: "memory");
}
__device__ __forceinline__ ull dup2(float w) {
    ull r;
    u32 wi = __float_as_uint(w);
    asm("mov.b64 %0, {%1, %1};" : "=l"(r) : "r"(wi));
    return r;
}
__device__ __forceinline__ void ffma2(ull& c, ull a, ull b) {
    asm("fma.rn.f32x2 %0, %1, %2, %0;" : "+l"(c) : "l"(a), "l"(b));
}
__device__ __forceinline__ void mma16816h(float* d, u32 a0, u32 a1, u32 a2, u32 a3,
                                          u32 b0, u32 b1) {
    asm volatile(
        "mma.sync.aligned.m16n8k16.row.col.f32.f16.f16.f32 "
        "{%0,%1,%2,%3}, {%4,%5,%6,%7}, {%8,%9}, {%0,%1,%2,%3};"
        : "+f"(d[0]), "+f"(d[1]), "+f"(d[2]), "+f"(d[3])
        : "r"(a0), "r"(a1), "r"(a2), "r"(a3), "r"(b0), "r"(b1));
}
__device__ __forceinline__ void ldmx4(u32& r0, u32& r1, u32& r2, u32& r3, u32 addr) {
    asm volatile(
        "ldmatrix.sync.aligned.m8n8.x4.shared.b16 {%0,%1,%2,%3}, [%4];"
        : "=r"(r0), "=r"(r1), "=r"(r2), "=r"(r3) : "r"(addr));
}
__device__ __forceinline__ void bar_sync(int id, int cnt) {
    asm volatile("bar.sync %0, %1;" :: "r"(id), "r"(cnt) : "memory");
}
__device__ __forceinline__ void bar_arrive(int id, int cnt) {
    asm volatile("bar.arrive %0, %1;" :: "r"(id), "r"(cnt) : "memory");
}

// ------------------- generic tiled GEMM (f32x2 + prefetch) -----------------
__global__ void __launch_bounds__(256) gemm_kernel(
    const float* __restrict__ A, const float* __restrict__ W,
    const float* __restrict__ bias, float* __restrict__ C,
    int M, int Nn, int K, int relu)
{
    __shared__ __align__(16) float As[16][68];
    __shared__ __align__(16) float Ws[16][68];

    int tid = threadIdx.x;
    int tx = tid & 15, ty = tid >> 4;
    int m0 = blockIdx.y * 64, n0 = blockIdx.x * 64;

    ull accp[4][2];
#pragma unroll
    for (int r = 0; r < 4; r++) { accp[r][0] = 0ull; accp[r][1] = 0ull; }

    int lr = tid >> 2;
    int lc = (tid & 3) * 4;
    const float* Ap = A + (size_t)(m0 + lr) * K + lc;
    bool wvalid = (n0 + lr) < Nn;
    const float* Wp = W + (size_t)(n0 + lr) * K + lc;

    float4 av = *(const float4*)(Ap);
    float4 wv = wvalid ? *(const float4*)(Wp) : make_float4(0.f, 0.f, 0.f, 0.f);

    for (int k0 = 0; k0 < K; k0 += 16) {
        __syncthreads();
        As[lc + 0][lr] = av.x; As[lc + 1][lr] = av.y;
        As[lc + 2][lr] = av.z; As[lc + 3][lr] = av.w;
        Ws[lc + 0][lr] = wv.x; Ws[lc + 1][lr] = wv.y;
        Ws[lc + 2][lr] = wv.z; Ws[lc + 3][lr] = wv.w;
        // prefetch next k-slab BEFORE compute so latency hides behind FFMAs
        float4 av2 = av, wv2 = wv;
        if (k0 + 16 < K) {
            av2 = *(const float4*)(Ap + k0 + 16);
            wv2 = wvalid ? *(const float4*)(Wp + k0 + 16)
                         : make_float4(0.f, 0.f, 0.f, 0.f);
        }
        __syncthreads();
#pragma unroll
        for (int kk = 0; kk < 16; kk++) {
            float4 a4 = *(const float4*)&As[kk][ty * 4];
            const ull* bp = (const ull*)&Ws[kk][tx * 4];
            ull b0 = bp[0], b1 = bp[1];
            ull ax = dup2(a4.x), ay = dup2(a4.y), az = dup2(a4.z), aw = dup2(a4.w);
            ffma2(accp[0][0], ax, b0); ffma2(accp[0][1], ax, b1);
            ffma2(accp[1][0], ay, b0); ffma2(accp[1][1], ay, b1);
            ffma2(accp[2][0], az, b0); ffma2(accp[2][1], az, b1);
            ffma2(accp[3][0], aw, b0); ffma2(accp[3][1], aw, b1);
        }
        av = av2; wv = wv2;
    }
#pragma unroll
    for (int r = 0; r < 4; r++) {
        int m = m0 + ty * 4 + r;
        float cvals[4];
        float2 lo = *reinterpret_cast<float2*>(&accp[r][0]);
        float2 hi = *reinterpret_cast<float2*>(&accp[r][1]);
        cvals[0] = lo.x; cvals[1] = lo.y; cvals[2] = hi.x; cvals[3] = hi.y;
#pragma unroll
        for (int c = 0; c < 4; c++) {
            int n = n0 + tx * 4 + c;
            if (n < Nn) {
                float v = cvals[c] + (bias ? bias[n] : 0.f);
                if (relu) v = fmaxf(v, 0.f);
                C[(size_t)m * Nn + n] = v;
            }
        }
    }
}

// --------- s/exp tables + per-tile swizzled fp16 B (one tau per block) ------
__global__ void __launch_bounds__(64) sab_kernel(const float* __restrict__ avec)
{
    extern __shared__ __align__(16) u32 st[];        // 2048 u32 = 8KB (one tau)
    int tid = threadIdx.x;                           // 0..63
    int j = blockIdx.x * 64 + tid;

    float v[DH];
    const float4* w4 = (const float4*)(g_Wh + (size_t)j * DH);
    float acc = 0.f;
#pragma unroll
    for (int q = 0; q < DH / 4; q++) {
        float4 wv = w4[q];
        float4 av = ((const float4*)avec)[q];
        v[q * 4 + 0] = wv.x; v[q * 4 + 1] = wv.y;
        v[q * 4 + 2] = wv.z; v[q * 4 + 3] = wv.w;
        acc += wv.x * av.x + wv.y * av.y + wv.z * av.z + wv.w * av.w;
    }
    g_s[j]  = acc;
    g_ea[j] = expf(acc);
    g_eb[j] = expf(0.2f * acc);

    int half = tid & 1, w = tid >> 1;
    __half* B = (__half*)st;
#pragma unroll
    for (int d = 0; d < DH; d++) {
        int widx = d * 32 + (w ^ (4 * (d & 7)));
        B[widx * 2 + half] = __float2half_rn(v[d]);
    }
    {
        int widx = 48 * 32 + w;                      // Z ones column (48&7==0)
        B[widx * 2 + half] = __float2half_rn(1.0f);
    }
#pragma unroll
    for (int d = 49; d < 64; d++) {
        int widx = d * 32 + (w ^ (4 * (d & 7)));
        B[widx * 2 + half] = __float2half_rn(0.0f);
    }
    __syncthreads();

    uint4* dst = (uint4*)(g_Bsw + (size_t)blockIdx.x * 2048);
    const uint4* src = (const uint4*)st;
#pragma unroll
    for (int it = 0; it < 8; it++)
        dst[tid + it * 64] = src[tid + it * 64];
}

// ------------- HMMA attention (warp-specialized, fused LN epilogue) --------
// SMEM (bytes)
#define SM_ISL 0                    // si[128]@0 eai@512 ebi@1024
#define SM_JSL 1536                 // 2 stages x 768 (sj@0 eaj@256 ebj@512)
#define SM_A   4096                 // 2 stages x 16KB (128 rows x 128B swizzled fp16)
#define SM_B   36864                // 2 stages x 8KB
#define SM_TOTAL 53248

// barrier ids: 2/3 = ready(stage), 4/5 = consumed(stage), 6 = producer-local

__global__ void __launch_bounds__(256, 2) attn_hmma_kernel(
    const int* __restrict__ adj,
    const float* __restrict__ gamma, const float* __restrict__ beta)
{
    extern __shared__ __align__(16) char sm[];
    __shared__ int s_last;
    u32 smb = (u32)__cvta_generic_to_shared(sm);
    int tid = threadIdx.x;
    int bx = blockIdx.x;
    int I0 = (bx >> 2) * 128;
    int jq = bx & 3;
    int tau0 = jq * TTILES;
    int jbase = jq * (NN / KSPLIT);

    if (tid >= 128) {
        // ========================= PRODUCER =========================
        int ptid = tid - 128;
        int c4 = (ptid & 15) << 2;       // fixed 4 j-columns
        int rbase = ptid >> 4;           // 0..7
        u32 wsbase = (u32)((c4 >> 1) ^ (4 * rbase));   // row&7 == rbase always

        // prologue copies: isl + B(0) + jsl(0)
        if (ptid < 96) {
            int table = ptid >> 5, idx = ptid & 31;
            const float* tp = (table == 0) ? g_s : (table == 1) ? g_ea : g_eb;
            cpa16(sm + SM_ISL + table * 512 + idx * 16, tp + I0 + idx * 4);
        }
        {
            const u32* src = g_Bsw + (size_t)tau0 * 2048;
#pragma unroll
            for (int k = 0; k < 4; k++) {
                int chunk = ptid + k * 128;
                cpa16(sm + SM_B + chunk * 16, src + chunk * 4);
            }
            if (ptid < 48) {
                int table = ptid >> 4, idx = ptid & 15;
                const float* tp = (table == 0) ? g_s : (table == 1) ? g_ea : g_eb;
                cpa16(sm + SM_JSL + table * 256 + idx * 16, tp + tau0 * 64 + idx * 4);
            }
        }
        cpa_commit();

        // adj prefetch tile 0
        int4 adjc[16];
#pragma unroll
        for (int p = 0; p < 16; p++)
            adjc[p] = *(const int4*)(adj + (size_t)(I0 + rbase + p * 8) * NN + jbase + c4);

        for (int t = 0; t < TTILES; t++) {
            int s = t & 1;
            if (t >= 2)
                bar_sync(4 + s, 256);    // A/B stage s consumed

            cpa_wait0();                 // B(t)/jsl(t)/(isl at t=0) landed
            bar_sync(6, 128);            // producer-local: copies visible

            const char* jsl = sm + SM_JSL + s * 768;
            float4 sjr = *(const float4*)(jsl + c4 * 4);
            float4 ear = *(const float4*)(jsl + 256 + c4 * 4);
            float4 ebr = *(const float4*)(jsl + 512 + c4 * 4);
            char* Ad = sm + SM_A + s * 16384;
            const float* isl0 = (const float*)(sm + SM_ISL);
#pragma unroll
            for (int p = 0; p < 16; p++) {
                int row = rbase + p * 8;
                float si  = isl0[row];
                float eai = isl0[128 + row];
                float ebi = isl0[256 + row];
                int4 a = adjc[p];
                float w0 = (si + sjr.x > 0.f) ? (eai * ear.x) : (ebi * ebr.x); if (!a.x) w0 = 0.f;
                float w1 = (si + sjr.y > 0.f) ? (eai * ear.y) : (ebi * ebr.y); if (!a.y) w1 = 0.f;
                float w2 = (si + sjr.z > 0.f) ? (eai * ear.z) : (ebi * ebr.z); if (!a.z) w2 = 0.f;
                float w3 = (si + sjr.w > 0.f) ? (eai * ear.w) : (ebi * ebr.w); if (!a.w) w3 = 0.f;
                __half2 hA = __floats2half2_rn(w0, w1);
                __half2 hB = __floats2half2_rn(w2, w3);
                uint2 hv;
                hv.x = *reinterpret_cast<u32*>(&hA);
                hv.y = *reinterpret_cast<u32*>(&hB);
                *(uint2*)(Ad + row * 128 + wsbase * 4) = hv;
            }
            asm volatile("membar.cta;" ::: "memory");
            bar_arrive(2 + s, 256);      // stage s ready

            if (t + 1 < TTILES) {
                const u32* src = g_Bsw + (size_t)(tau0 + t + 1) * 2048;
                char* Bst = sm + SM_B + (s ^ 1) * 8192;
#pragma unroll
                for (int k = 0; k < 4; k++) {
                    int chunk = ptid + k * 128;
                    cpa16(Bst + chunk * 16, src + chunk * 4);
                }
                if (ptid < 48) {
                    int table = ptid >> 4, idx = ptid & 15;
                    const float* tp = (table == 0) ? g_s : (table == 1) ? g_ea : g_eb;
                    cpa16(sm + SM_JSL + (s ^ 1) * 768 + table * 256 + idx * 16,
                          tp + (tau0 + t + 1) * 64 + idx * 4);
                }
                cpa_commit();
                int J = jbase + (t + 1) * 64;
#pragma unroll
                for (int p = 0; p < 16; p++)
                    adjc[p] = *(const int4*)(adj + (size_t)(I0 + rbase + p * 8) * NN + J + c4);
            }
        }
    } else {
        // ========================= CONSUMER =========================
        int lane = tid & 31, cw = tid >> 5;   // cw 0..3, owns rows [cw*32, cw*32+32)
        int gid = lane >> 2, tig = lane & 3;
        int r7 = lane & 7;
        int ak4 = ((lane >> 4) & 1) * 4;

        u32 aaddr[2][4];
#pragma unroll
        for (int m = 0; m < 2; m++) {
            int arow = cw * 32 + m * 16 + ((lane >> 3) & 1) * 8 + r7;
#pragma unroll
            for (int c = 0; c < 4; c++)
                aaddr[m][c] = smb + SM_A + arow * 128 + (u32)(((8 * c + ak4) ^ (4 * r7)) * 4);
        }
        u32 boffp[4];
        {
            int bk4 = ((lane >> 3) & 1) * 4;
            int bnb = ((lane >> 4) & 1) * 1024;
#pragma unroll
            for (int c = 0; c < 4; c++)
                boffp[c] = (u32)(bnb + r7 * 128 + ((8 * c + bk4) ^ (4 * r7)) * 4);
        }

        float acc[2][7][4];
#pragma unroll
        for (int m = 0; m < 2; m++)
#pragma unroll
            for (int nb = 0; nb < 7; nb++)
#pragma unroll
                for (int q = 0; q < 4; q++) acc[m][nb][q] = 0.f;

        for (int t = 0; t < TTILES; t++) {
            int s = t & 1;
            bar_sync(2 + s, 256);        // stage s ready
            u32 Aoff = (u32)(s * 16384);
            u32 Bst = smb + SM_B + (u32)(s * 8192);
#pragma unroll
            for (int c = 0; c < 4; c++) {
                u32 a00, a01, a02, a03, a10, a11, a12, a13;
                ldmx4(a00, a01, a02, a03, aaddr[0][c] + Aoff);
                ldmx4(a10, a11, a12, a13, aaddr[1][c] + Aoff);
#pragma unroll
                for (int np = 0; np < 4; np++) {
                    u32 b00, b01, b10, b11;
                    ldmx4(b00, b01, b10, b11, Bst + boffp[c] + (u32)(np * 2048));
                    mma16816h(acc[0][np * 2], a00, a01, a02, a03, b00, b01);
                    mma16816h(acc[1][np * 2], a10, a11, a12, a13, b00, b01);
                    if (np < 3) {
                        mma16816h(acc[0][np * 2 + 1], a00, a01, a02, a03, b10, b11);
                        mma16816h(acc[1][np * 2 + 1], a10, a11, a12, a13, b10, b11);
                    }
                }
            }
            bar_arrive(4 + s, 256);      // stage s consumed
        }

        // write partials
#pragma unroll
        for (int m = 0; m < 2; m++) {
            float* dst = g_part + ((size_t)bx * 128 + cw * 32 + m * 16 + gid) * 64;
#pragma unroll
            for (int nb = 0; nb < 7; nb++) {
                int col = nb * 8 + tig * 2;
                *(float2*)(dst + col) = make_float2(acc[m][nb][0], acc[m][nb][1]);
                *(float2*)(dst + 8 * 64 + col) = make_float2(acc[m][nb][2], acc[m][nb][3]);
            }
        }
    }

    // ============== fused reduce + normalize + LayerNorm (last CTA) =========
    __syncthreads();                     // all partial STGs issued CTA-wide
    if (tid == 0) {
        __threadfence();
        int old = atomicAdd(&g_cnt[bx >> 2], 1);
        s_last = (old == 3);
    }
    __syncthreads();
    if (s_last) {
        int itile = bx >> 2;
        if (tid == 0) g_cnt[itile] = 0;  // reset for next graph replay

        int r = tid >> 1, half = tid & 1;    // 2 threads per row, 128 rows
        const float* p0 = g_part + ((size_t)(itile * 4 + 0) * 128 + r) * 64;
        const float* p1 = g_part + ((size_t)(itile * 4 + 1) * 128 + r) * 64;
        const float* p2 = g_part + ((size_t)(itile * 4 + 2) * 128 + r) * 64;
        const float* p3 = g_part + ((size_t)(itile * 4 + 3) * 128 + r) * 64;

        float4 v[6];
#pragma unroll
        for (int k = 0; k < 6; k++) {
            int q = half + 2 * k;
            float4 a = ((const float4*)p0)[q];
            float4 b = ((const float4*)p1)[q];
            float4 c = ((const float4*)p2)[q];
            float4 d = ((const float4*)p3)[q];
            v[k].x = (a.x + b.x) + (c.x + d.x);
            v[k].y = (a.y + b.y) + (c.y + d.y);
            v[k].z = (a.z + b.z) + (c.z + d.z);
            v[k].w = (a.w + b.w) + (c.w + d.w);
        }
        float Z = 0.f;
        if (half == 0)
            Z = (p0[48] + p1[48]) + (p2[48] + p3[48]);
        float Zo = __shfl_xor_sync(0xffffffffu, Z, 1);
        if (half == 1) Z = Zo;
        float rz = 1.0f / Z;

        float s1 = 0.f;
#pragma unroll
        for (int k = 0; k < 6; k++) {
            v[k].x *= rz; v[k].y *= rz; v[k].z *= rz; v[k].w *= rz;
            s1 += (v[k].x + v[k].y) + (v[k].z + v[k].w);
        }
        s1 += __shfl_xor_sync(0xffffffffu, s1, 1);
        float mu = s1 * (1.0f / DH);
        float s2 = 0.f;
#pragma unroll
        for (int k = 0; k < 6; k++) {
            float d0 = v[k].x - mu, d1 = v[k].y - mu, d2 = v[k].z - mu, d3 = v[k].w - mu;
            s2 += (d0 * d0 + d1 * d1) + (d2 * d2 + d3 * d3);
        }
        s2 += __shfl_xor_sync(0xffffffffu, s2, 1);
        float rstd = rsqrtf(s2 * (1.0f / DH) + 1e-5f);

        float* o = g_hn + (size_t)(itile * 128 + r) * DH;
#pragma unroll
        for (int k = 0; k < 6; k++) {
            int q = half + 2 * k;
            float4 ov;
            ov.x = (v[k].x - mu) * rstd * gamma[q * 4 + 0] + beta[q * 4 + 0];
            ov.y = (v[k].y - mu) * rstd * gamma[q * 4 + 1] + beta[q * 4 + 1];
            ov.z = (v[k].z - mu) * rstd * gamma[q * 4 + 2] + beta[q * 4 + 2];
            ov.w = (v[k].w - mu) * rstd * gamma[q * 4 + 3] + beta[q * 4 + 3];
            *(float4*)(o + q * 4) = ov;
        }
    }
}

// ------------------------- launch ------------------------------------------
extern "C" void kernel_launch(void* const* d_in, const int* in_sizes, int n_in,
                              void* d_out, int out_size)
{
    const float* x     = (const float*)d_in[0];
    const int*   adj   = (const int*)  d_in[1];
    const float* Wg    = (const float*)d_in[2];
    const float* avec  = (const float*)d_in[3];
    const float* gamma = (const float*)d_in[4];
    const float* beta  = (const float*)d_in[5];
    const float* W1    = (const float*)d_in[6];
    const float* b1    = (const float*)d_in[7];
    const float* W2    = (const float*)d_in[8];
    const float* b2    = (const float*)d_in[9];
    const float* W3    = (const float*)d_in[10];
    const float* b3    = (const float*)d_in[11];
    float* out = (float*)d_out;

    float *Wh, *hn, *m1, *m2;
    cudaGetSymbolAddress((void**)&Wh, g_Wh);
    cudaGetSymbolAddress((void**)&hn, g_hn);
    cudaGetSymbolAddress((void**)&m1, g_m1);
    cudaGetSymbolAddress((void**)&m2, g_m2);

    static int smem_set = 0;
    if (!smem_set) {
        cudaFuncSetAttribute(attn_hmma_kernel,
                             cudaFuncAttributeMaxDynamicSharedMemorySize, SM_TOTAL);
        cudaFuncSetAttribute(sab_kernel,
                             cudaFuncAttributeMaxDynamicSharedMemorySize, 8192);
        smem_set = 1;
    }

    // Wh = x @ W_gat^T   [8192 x 48]
    gemm_kernel<<<dim3(1, NN / 64), 256>>>(x, Wg, nullptr, Wh, NN, DH, DIN, 0);
    // s, exp tables, per-tile swizzled fp16 B (one tau per block)
    sab_kernel<<<128, 64, 8192>>>(avec);
    // warp-specialized HMMA attention + fused LN -> g_hn  (grid 256, 2 CTAs/SM)
    attn_hmma_kernel<<<NN / 128 * KSPLIT, 256, SM_TOTAL>>>(adj, gamma, beta);
    // MLP head
    gemm_kernel<<<dim3(DH1 / 64, NN / 64), 256>>>(hn, W1, b1, m1, NN, DH1, DH, 1);
    gemm_kernel<<<dim3(DH2 / 64, NN / 64), 256>>>(m1, W2, b2, m2, NN, DH2, DH1, 1);
    gemm_kernel<<<dim3(1, NN / 64), 256>>>(m2, W3, b3, out, NN, DOUT, DH2, 0);
}

// round 16
// speedup vs baseline: 1.4059x; 1.4059x over previous
#include <cuda_runtime.h>
#include <cuda_fp16.h>
#include <math.h>
#include <stdint.h>

#define NN   8192
#define DIN  128
#define DH   48
#define DH1  256
#define DH2  128
#define DOUT 32

#define KSPLIT  4
#define TTILES  32            // j-tiles of 64 per K-quarter

typedef unsigned int u32;
typedef unsigned long long ull;

// ------------------------- scratch (device globals; no allocs) -------------
__device__ float g_Wh[NN * DH];
__device__ float g_s[NN];
__device__ float g_ea[NN];
__device__ float g_eb[NN];
__device__ __align__(16) u32 g_Bsw[128 * 2048];  // per-tile swizzled B fp16 (1 MB)
__device__ float g_part[256 * 128 * 64];         // per-CTA partial D (Z at col 48)
__device__ float g_hn[NN * DH];
__device__ float g_m1[NN * DH1];
__device__ float g_m2[NN * DH2];

// ------------------------- PTX helpers -------------------------------------
__device__ __forceinline__ void cpa16(void* dst_smem, const void* src) {
    u32 d = (u32)__cvta_generic_to_shared(dst_smem);
    asm volatile("cp.async.cg.shared.global [%0], [%1], 16;" :: "r"(d), "l"(src));
}
__device__ __forceinline__ void cpa_commit() {
    asm volatile("cp.async.commit_group;" ::: "memory");
}
__device__ __forceinline__ void cpa_wait0() {
    asm volatile("cp.async.wait_group 0;" ::: "memory");
}
__device__ __forceinline__ ull dup2(float w) {
    ull r;
    u32 wi = __float_as_uint(w);
    asm("mov.b64 %0, {%1, %1};" : "=l"(r) : "r"(wi));
    return r;
}
__device__ __forceinline__ void ffma2(ull& c, ull a, ull b) {
    asm("fma.rn.f32x2 %0, %1, %2, %0;" : "+l"(c) : "l"(a), "l"(b));
}
__device__ __forceinline__ void mma16816h(float* d, u32 a0, u32 a1, u32 a2, u32 a3,
                                          u32 b0, u32 b1) {
    asm volatile(
        "mma.sync.aligned.m16n8k16.row.col.f32.f16.f16.f32 "
        "{%0,%1,%2,%3}, {%4,%5,%6,%7}, {%8,%9}, {%0,%1,%2,%3};"
        : "+f"(d[0]), "+f"(d[1]), "+f"(d[2]), "+f"(d[3])
        : "r"(a0), "r"(a1), "r"(a2), "r"(a3), "r"(b0), "r"(b1));
}
__device__ __forceinline__ void ldmx4(u32& r0, u32& r1, u32& r2, u32& r3, u32 addr) {
    asm volatile(
        "ldmatrix.sync.aligned.m8n8.x4.shared.b16 {%0,%1,%2,%3}, [%4];"
        : "=r"(r0), "=r"(r1), "=r"(r2), "=r"(r3) : "r"(addr));
}
__device__ __forceinline__ void bar_sync(int id, int cnt) {
    asm volatile("bar.sync %0, %1;" :: "r"(id), "r"(cnt) : "memory");
}
__device__ __forceinline__ void bar_arrive(int id, int cnt) {
    asm volatile("bar.arrive %0, %1;" :: "r"(id), "r"(cnt) : "memory");
}

// ------------------------- generic tiled GEMM (f32x2 inner) ----------------
__global__ void __launch_bounds__(256) gemm_kernel(
    const float* __restrict__ A, const float* __restrict__ W,
    const float* __restrict__ bias, float* __restrict__ C,
    int M, int Nn, int K, int relu)
{
    __shared__ __align__(16) float As[16][68];
    __shared__ __align__(16) float Ws[16][68];

    int tid = threadIdx.x;
    int tx = tid & 15, ty = tid >> 4;
    int m0 = blockIdx.y * 64, n0 = blockIdx.x * 64;

    ull accp[4][2];
#pragma unroll
    for (int r = 0; r < 4; r++) { accp[r][0] = 0ull; accp[r][1] = 0ull; }

    int lr = tid >> 2;
    int lc = (tid & 3) * 4;
    const float* Ap = A + (size_t)(m0 + lr) * K + lc;
    bool wvalid = (n0 + lr) < Nn;
    const float* Wp = W + (size_t)(n0 + lr) * K + lc;

    for (int k0 = 0; k0 < K; k0 += 16) {
        float4 av = *(const float4*)(Ap + k0);
        float4 wv = wvalid ? *(const float4*)(Wp + k0) : make_float4(0.f, 0.f, 0.f, 0.f);
        __syncthreads();
        As[lc + 0][lr] = av.x; As[lc + 1][lr] = av.y;
        As[lc + 2][lr] = av.z; As[lc + 3][lr] = av.w;
        Ws[lc + 0][lr] = wv.x; Ws[lc + 1][lr] = wv.y;
        Ws[lc + 2][lr] = wv.z; Ws[lc + 3][lr] = wv.w;
        __syncthreads();
#pragma unroll
        for (int kk = 0; kk < 16; kk++) {
            float4 a4 = *(const float4*)&As[kk][ty * 4];
            const ull* bp = (const ull*)&Ws[kk][tx * 4];
            ull b0 = bp[0], b1 = bp[1];
            ull ax = dup2(a4.x), ay = dup2(a4.y), az = dup2(a4.z), aw = dup2(a4.w);
            ffma2(accp[0][0], ax, b0); ffma2(accp[0][1], ax, b1);
            ffma2(accp[1][0], ay, b0); ffma2(accp[1][1], ay, b1);
            ffma2(accp[2][0], az, b0); ffma2(accp[2][1], az, b1);
            ffma2(accp[3][0], aw, b0); ffma2(accp[3][1], aw, b1);
        }
    }
#pragma unroll
    for (int r = 0; r < 4; r++) {
        int m = m0 + ty * 4 + r;
        float cvals[4];
        float2 lo = *reinterpret_cast<float2*>(&accp[r][0]);
        float2 hi = *reinterpret_cast<float2*>(&accp[r][1]);
        cvals[0] = lo.x; cvals[1] = lo.y; cvals[2] = hi.x; cvals[3] = hi.y;
#pragma unroll
        for (int c = 0; c < 4; c++) {
            int n = n0 + tx * 4 + c;
            if (n < Nn) {
                float v = cvals[c] + (bias ? bias[n] : 0.f);
                if (relu) v = fmaxf(v, 0.f);
                C[(size_t)m * Nn + n] = v;
            }
        }
    }
}

// --------- s/exp tables + per-tile swizzled fp16 B (one tau per block) ------
__global__ void __launch_bounds__(64) sab_kernel(const float* __restrict__ avec)
{
    extern __shared__ __align__(16) u32 st[];        // 2048 u32 = 8KB (one tau)
    int tid = threadIdx.x;                           // 0..63
    int j = blockIdx.x * 64 + tid;

    float v[DH];
    const float4* w4 = (const float4*)(g_Wh + (size_t)j * DH);
    float acc = 0.f;
#pragma unroll
    for (int q = 0; q < DH / 4; q++) {
        float4 wv = w4[q];
        float4 av = ((const float4*)avec)[q];
        v[q * 4 + 0] = wv.x; v[q * 4 + 1] = wv.y;
        v[q * 4 + 2] = wv.z; v[q * 4 + 3] = wv.w;
        acc += wv.x * av.x + wv.y * av.y + wv.z * av.z + wv.w * av.w;
    }
    g_s[j]  = acc;
    g_ea[j] = expf(acc);
    g_eb[j] = expf(0.2f * acc);

    int half = tid & 1, w = tid >> 1;
    __half* B = (__half*)st;
#pragma unroll
    for (int d = 0; d < DH; d++) {
        int widx = d * 32 + (w ^ (4 * (d & 7)));
        B[widx * 2 + half] = __float2half_rn(v[d]);
    }
    {
        int widx = 48 * 32 + w;                      // Z ones column (48&7==0)
        B[widx * 2 + half] = __float2half_rn(1.0f);
    }
#pragma unroll
    for (int d = 49; d < 64; d++) {
        int widx = d * 32 + (w ^ (4 * (d & 7)));
        B[widx * 2 + half] = __float2half_rn(0.0f);
    }
    __syncthreads();

    uint4* dst = (uint4*)(g_Bsw + (size_t)blockIdx.x * 2048);
    const uint4* src = (const uint4*)st;
#pragma unroll
    for (int it = 0; it < 8; it++)
        dst[tid + it * 64] = src[tid + it * 64];
}

// ------------------- HMMA attention (warp-specialized) ---------------------
// SMEM (bytes)
#define SM_ISL 0                    // si[128]@0 eai@512 ebi@1024
#define SM_JSL 1536                 // 2 stages x 768 (sj@0 eaj@256 ebj@512)
#define SM_A   4096                 // 2 stages x 16KB (128 rows x 128B swizzled fp16)
#define SM_B   36864                // 2 stages x 8KB
#define SM_TOTAL 53248

// barrier ids: 2/3 = ready(stage), 4/5 = consumed(stage), 6 = producer-local

__global__ void __launch_bounds__(256, 2) attn_hmma_kernel(const int* __restrict__ adj)
{
    extern __shared__ __align__(16) char sm[];
    u32 smb = (u32)__cvta_generic_to_shared(sm);
    int tid = threadIdx.x;
    int bx = blockIdx.x;
    int I0 = (bx >> 2) * 128;
    int jq = bx & 3;
    int tau0 = jq * TTILES;
    int jbase = jq * (NN / KSPLIT);

    if (tid >= 128) {
        // ========================= PRODUCER =========================
        int ptid = tid - 128;
        int c4 = (ptid & 15) << 2;       // fixed 4 j-columns
        int rbase = ptid >> 4;           // 0..7
        u32 wsbase = (u32)((c4 >> 1) ^ (4 * rbase));   // row&7 == rbase always

        // prologue copies: isl + B(0) + jsl(0)
        if (ptid < 96) {
            int table = ptid >> 5, idx = ptid & 31;
            const float* tp = (table == 0) ? g_s : (table == 1) ? g_ea : g_eb;
            cpa16(sm + SM_ISL + table * 512 + idx * 16, tp + I0 + idx * 4);
        }
        {
            const u32* src = g_Bsw + (size_t)tau0 * 2048;
#pragma unroll
            for (int k = 0; k < 4; k++) {
                int chunk = ptid + k * 128;
                cpa16(sm + SM_B + chunk * 16, src + chunk * 4);
            }
            if (ptid < 48) {
                int table = ptid >> 4, idx = ptid & 15;
                const float* tp = (table == 0) ? g_s : (table == 1) ? g_ea : g_eb;
                cpa16(sm + SM_JSL + table * 256 + idx * 16, tp + tau0 * 64 + idx * 4);
            }
        }
        cpa_commit();

        // adj prefetch tile 0
        int4 adjc[16];
#pragma unroll
        for (int p = 0; p < 16; p++)
            adjc[p] = *(const int4*)(adj + (size_t)(I0 + rbase + p * 8) * NN + jbase + c4);

        for (int t = 0; t < TTILES; t++) {
            int s = t & 1;
            if (t >= 2)
                bar_sync(4 + s, 256);    // A/B stage s consumed

            cpa_wait0();                 // B(t)/jsl(t)/(isl at t=0) landed
            bar_sync(6, 128);            // producer-local: copies visible

            const char* jsl = sm + SM_JSL + s * 768;
            float4 sjr = *(const float4*)(jsl + c4 * 4);
            float4 ear = *(const float4*)(jsl + 256 + c4 * 4);
            float4 ebr = *(const float4*)(jsl + 512 + c4 * 4);
            char* Ad = sm + SM_A + s * 16384;
            const float* isl0 = (const float*)(sm + SM_ISL);
#pragma unroll
            for (int p = 0; p < 16; p++) {
                int row = rbase + p * 8;
                float si  = isl0[row];
                float eai = isl0[128 + row];
                float ebi = isl0[256 + row];
                int4 a = adjc[p];
                float w0 = (si + sjr.x > 0.f) ? (eai * ear.x) : (ebi * ebr.x); if (!a.x) w0 = 0.f;
                float w1 = (si + sjr.y > 0.f) ? (eai * ear.y) : (ebi * ebr.y); if (!a.y) w1 = 0.f;
                float w2 = (si + sjr.z > 0.f) ? (eai * ear.z) : (ebi * ebr.z); if (!a.z) w2 = 0.f;
                float w3 = (si + sjr.w > 0.f) ? (eai * ear.w) : (ebi * ebr.w); if (!a.w) w3 = 0.f;
                __half2 hA = __floats2half2_rn(w0, w1);
                __half2 hB = __floats2half2_rn(w2, w3);
                uint2 hv;
                hv.x = *reinterpret_cast<u32*>(&hA);
                hv.y = *reinterpret_cast<u32*>(&hB);
                *(uint2*)(Ad + row * 128 + wsbase * 4) = hv;
            }
            asm volatile("membar.cta;" ::: "memory");
            bar_arrive(2 + s, 256);      // stage s ready

            if (t + 1 < TTILES) {
                const u32* src = g_Bsw + (size_t)(tau0 + t + 1) * 2048;
                char* Bst = sm + SM_B + (s ^ 1) * 8192;
#pragma unroll
                for (int k = 0; k < 4; k++) {
                    int chunk = ptid + k * 128;
                    cpa16(Bst + chunk * 16, src + chunk * 4);
                }
                if (ptid < 48) {
                    int table = ptid >> 4, idx = ptid & 15;
                    const float* tp = (table == 0) ? g_s : (table == 1) ? g_ea : g_eb;
                    cpa16(sm + SM_JSL + (s ^ 1) * 768 + table * 256 + idx * 16,
                          tp + (tau0 + t + 1) * 64 + idx * 4);
                }
                cpa_commit();
                int J = jbase + (t + 1) * 64;
#pragma unroll
                for (int p = 0; p < 16; p++)
                    adjc[p] = *(const int4*)(adj + (size_t)(I0 + rbase + p * 8) * NN + J + c4);
            }
        }
    } else {
        // ========================= CONSUMER =========================
        int lane = tid & 31, cw = tid >> 5;   // cw 0..3, owns rows [cw*32, cw*32+32)
        int gid = lane >> 2, tig = lane & 3;
        int r7 = lane & 7;
        int ak4 = ((lane >> 4) & 1) * 4;

        u32 aaddr[2][4];
#pragma unroll
        for (int m = 0; m < 2; m++) {
            int arow = cw * 32 + m * 16 + ((lane >> 3) & 1) * 8 + r7;
#pragma unroll
            for (int c = 0; c < 4; c++)
                aaddr[m][c] = smb + SM_A + arow * 128 + (u32)(((8 * c + ak4) ^ (4 * r7)) * 4);
        }
        u32 boffp[4];
        {
            int bk4 = ((lane >> 3) & 1) * 4;
            int bnb = ((lane >> 4) & 1) * 1024;
#pragma unroll
            for (int c = 0; c < 4; c++)
                boffp[c] = (u32)(bnb + r7 * 128 + ((8 * c + bk4) ^ (4 * r7)) * 4);
        }

        float acc[2][7][4];
#pragma unroll
        for (int m = 0; m < 2; m++)
#pragma unroll
            for (int nb = 0; nb < 7; nb++)
#pragma unroll
                for (int q = 0; q < 4; q++) acc[m][nb][q] = 0.f;

        for (int t = 0; t < TTILES; t++) {
            int s = t & 1;
            bar_sync(2 + s, 256);        // stage s ready
            u32 Aoff = (u32)(s * 16384);
            u32 Bst = smb + SM_B + (u32)(s * 8192);
#pragma unroll
            for (int c = 0; c < 4; c++) {
                u32 a00, a01, a02, a03, a10, a11, a12, a13;
                ldmx4(a00, a01, a02, a03, aaddr[0][c] + Aoff);
                ldmx4(a10, a11, a12, a13, aaddr[1][c] + Aoff);
#pragma unroll
                for (int np = 0; np < 4; np++) {
                    u32 b00, b01, b10, b11;
                    ldmx4(b00, b01, b10, b11, Bst + boffp[c] + (u32)(np * 2048));
                    mma16816h(acc[0][np * 2], a00, a01, a02, a03, b00, b01);
                    mma16816h(acc[1][np * 2], a10, a11, a12, a13, b00, b01);
                    if (np < 3) {
                        mma16816h(acc[0][np * 2 + 1], a00, a01, a02, a03, b10, b11);
                        mma16816h(acc[1][np * 2 + 1], a10, a11, a12, a13, b10, b11);
                    }
                }
            }
            bar_arrive(4 + s, 256);      // stage s consumed
        }

        // epilogue: write partials
#pragma unroll
        for (int m = 0; m < 2; m++) {
            float* dst = g_part + ((size_t)bx * 128 + cw * 32 + m * 16 + gid) * 64;
#pragma unroll
            for (int nb = 0; nb < 7; nb++) {
                int col = nb * 8 + tig * 2;
                *(float2*)(dst + col) = make_float2(acc[m][nb][0], acc[m][nb][1]);
                *(float2*)(dst + 8 * 64 + col) = make_float2(acc[m][nb][2], acc[m][nb][3]);
            }
        }
    }
}

// -------------------- reduce K-split + normalize + LayerNorm ----------------
__global__ void __launch_bounds__(256) reduce_ln_kernel(
    const float* __restrict__ gamma, const float* __restrict__ beta)
{
    int gt = blockIdx.x * 256 + threadIdx.x;     // 16384 threads
    int i = gt >> 1, half = gt & 1;
    int itile = i >> 7, r = i & 127;
    const float* p0 = g_part + ((size_t)(itile * 4 + 0) * 128 + r) * 64;
    const float* p1 = g_part + ((size_t)(itile * 4 + 1) * 128 + r) * 64;
    const float* p2 = g_part + ((size_t)(itile * 4 + 2) * 128 + r) * 64;
    const float* p3 = g_part + ((size_t)(itile * 4 + 3) * 128 + r) * 64;

    float4 v[6];
#pragma unroll
    for (int k = 0; k < 6; k++) {
        int q = half + 2 * k;
        float4 a = ((const float4*)p0)[q];
        float4 b = ((const float4*)p1)[q];
        float4 c = ((const float4*)p2)[q];
        float4 d = ((const float4*)p3)[q];
        v[k].x = (a.x + b.x) + (c.x + d.x);
        v[k].y = (a.y + b.y) + (c.y + d.y);
        v[k].z = (a.z + b.z) + (c.z + d.z);
        v[k].w = (a.w + b.w) + (c.w + d.w);
    }
    float Z = 0.f;
    if (half == 0)
        Z = (p0[48] + p1[48]) + (p2[48] + p3[48]);
    float Zo = __shfl_xor_sync(0xffffffffu, Z, 1);
    if (half == 1) Z = Zo;
    float rz = 1.0f / Z;

    float s1 = 0.f;
#pragma unroll
    for (int k = 0; k < 6; k++) {
        v[k].x *= rz; v[k].y *= rz; v[k].z *= rz; v[k].w *= rz;
        s1 += (v[k].x + v[k].y) + (v[k].z + v[k].w);
    }
    s1 += __shfl_xor_sync(0xffffffffu, s1, 1);
    float mu = s1 * (1.0f / DH);
    float s2 = 0.f;
#pragma unroll
    for (int k = 0; k < 6; k++) {
        float d0 = v[k].x - mu, d1 = v[k].y - mu, d2 = v[k].z - mu, d3 = v[k].w - mu;
        s2 += (d0 * d0 + d1 * d1) + (d2 * d2 + d3 * d3);
    }
    s2 += __shfl_xor_sync(0xffffffffu, s2, 1);
    float rstd = rsqrtf(s2 * (1.0f / DH) + 1e-5f);

    float* o = g_hn + (size_t)i * DH;
#pragma unroll
    for (int k = 0; k < 6; k++) {
        int q = half + 2 * k;
        float4 ov;
        ov.x = (v[k].x - mu) * rstd * gamma[q * 4 + 0] + beta[q * 4 + 0];
        ov.y = (v[k].y - mu) * rstd * gamma[q * 4 + 1] + beta[q * 4 + 1];
        ov.z = (v[k].z - mu) * rstd * gamma[q * 4 + 2] + beta[q * 4 + 2];
        ov.w = (v[k].w - mu) * rstd * gamma[q * 4 + 3] + beta[q * 4 + 3];
        *(float4*)(o + q * 4) = ov;
    }
}

// ------------------------- launch ------------------------------------------
extern "C" void kernel_launch(void* const* d_in, const int* in_sizes, int n_in,
                              void* d_out, int out_size)
{
    const float* x     = (const float*)d_in[0];
    const int*   adj   = (const int*)  d_in[1];
    const float* Wg    = (const float*)d_in[2];
    const float* avec  = (const float*)d_in[3];
    const float* gamma = (const float*)d_in[4];
    const float* beta  = (const float*)d_in[5];
    const float* W1    = (const float*)d_in[6];
    const float* b1    = (const float*)d_in[7];
    const float* W2    = (const float*)d_in[8];
    const float* b2    = (const float*)d_in[9];
    const float* W3    = (const float*)d_in[10];
    const float* b3    = (const float*)d_in[11];
    float* out = (float*)d_out;

    float *Wh, *hn, *m1, *m2;
    cudaGetSymbolAddress((void**)&Wh, g_Wh);
    cudaGetSymbolAddress((void**)&hn, g_hn);
    cudaGetSymbolAddress((void**)&m1, g_m1);
    cudaGetSymbolAddress((void**)&m2, g_m2);

    static int smem_set = 0;
    if (!smem_set) {
        cudaFuncSetAttribute(attn_hmma_kernel,
                             cudaFuncAttributeMaxDynamicSharedMemorySize, SM_TOTAL);
        cudaFuncSetAttribute(sab_kernel,
                             cudaFuncAttributeMaxDynamicSharedMemorySize, 8192);
        smem_set = 1;
    }

    // Wh = x @ W_gat^T   [8192 x 48]
    gemm_kernel<<<dim3(1, NN / 64), 256>>>(x, Wg, nullptr, Wh, NN, DH, DIN, 0);
    // s, exp tables, per-tile swizzled fp16 B (one tau per block, 128 CTAs)
    sab_kernel<<<128, 64, 8192>>>(avec);
    // warp-specialized HMMA attention -> g_part  (grid 256, 2 CTAs/SM)
    attn_hmma_kernel<<<NN / 128 * KSPLIT, 256, SM_TOTAL>>>(adj);
    // combine K-splits, normalize, LayerNorm -> g_hn
    reduce_ln_kernel<<<64, 256>>>(gamma, beta);
    // MLP head
    gemm_kernel<<<dim3(DH1 / 64, NN / 64), 256>>>(hn, W1, b1, m1, NN, DH1, DH, 1);
    gemm_kernel<<<dim3(DH2 / 64, NN / 64), 256>>>(m1, W2, b2, m2, NN, DH2, DH1, 1);
    gemm_kernel<<<dim3(1, NN / 64), 256>>>(m2, W3, b3, out, NN, DOUT, DH2, 0);
}

// round 17
// speedup vs baseline: 1.6805x; 1.1953x over previous
#include <cuda_runtime.h>
#include <cuda_fp16.h>
#include <math.h>
#include <stdint.h>

#define NN   8192
#define DIN  128
#define DH   48
#define DH1  256
#define DH2  128
#define DOUT 32

#define KSPLIT  4
#define TTILES  32            // j-tiles of 64 per K-quarter

typedef unsigned int u32;
typedef unsigned long long ull;

// ------------------------- scratch (device globals; no allocs) -------------
__device__ float g_Wh[NN * DH];
__device__ float g_s[NN];
__device__ float g_ea[NN];
__device__ float g_eb[NN];
__device__ __align__(16) u32 g_Bsw[128 * 2048];  // per-tile swizzled B fp16 (1 MB)
__device__ float g_part[256 * 128 * 64];         // per-CTA partial D (Z at col 48)
__device__ float g_hn[NN * DH];
__device__ float g_m1[NN * DH1];
__device__ float g_m2[NN * DH2];

// ------------------------- PTX helpers -------------------------------------
__device__ __forceinline__ void cpa16(void* dst_smem, const void* src) {
    u32 d = (u32)__cvta_generic_to_shared(dst_smem);
    asm volatile("cp.async.cg.shared.global [%0], [%1], 16;" :: "r"(d), "l"(src));
}
__device__ __forceinline__ void cpa_commit() {
    asm volatile("cp.async.commit_group;" ::: "memory");
}
__device__ __forceinline__ void cpa_wait0() {
    asm volatile("cp.async.wait_group 0;" ::: "memory");
}
__device__ __forceinline__ ull dup2(float w) {
    ull r;
    u32 wi = __float_as_uint(w);
    asm("mov.b64 %0, {%1, %1};" : "=l"(r) : "r"(wi));
    return r;
}
__device__ __forceinline__ void ffma2(ull& c, ull a, ull b) {
    asm("fma.rn.f32x2 %0, %1, %2, %0;" : "+l"(c) : "l"(a), "l"(b));
}
__device__ __forceinline__ void mma16816h(float* d, u32 a0, u32 a1, u32 a2, u32 a3,
                                          u32 b0, u32 b1) {
    asm volatile(
        "mma.sync.aligned.m16n8k16.row.col.f32.f16.f16.f32 "
        "{%0,%1,%2,%3}, {%4,%5,%6,%7}, {%8,%9}, {%0,%1,%2,%3};"
        : "+f"(d[0]), "+f"(d[1]), "+f"(d[2]), "+f"(d[3])
        : "r"(a0), "r"(a1), "r"(a2), "r"(a3), "r"(b0), "r"(b1));
}
__device__ __forceinline__ void ldmx4(u32& r0, u32& r1, u32& r2, u32& r3, u32 addr) {
    asm volatile(
        "ldmatrix.sync.aligned.m8n8.x4.shared.b16 {%0,%1,%2,%3}, [%4];"
        : "=r"(r0), "=r"(r1), "=r"(r2), "=r"(r3) : "r"(addr));
}
__device__ __forceinline__ void bar_sync(int id, int cnt) {
    asm volatile("bar.sync %0, %1;" :: "r"(id), "r"(cnt) : "memory");
}
__device__ __forceinline__ void bar_arrive(int id, int cnt) {
    asm volatile("bar.arrive %0, %1;" :: "r"(id), "r"(cnt) : "memory");
}

// ------------------------- generic tiled GEMM (f32x2 inner) ----------------
__global__ void __launch_bounds__(256) gemm_kernel(
    const float* __restrict__ A, const float* __restrict__ W,
    const float* __restrict__ bias, float* __restrict__ C,
    int M, int Nn, int K, int relu)
{
    __shared__ __align__(16) float As[16][68];
    __shared__ __align__(16) float Ws[16][68];

    int tid = threadIdx.x;
    int tx = tid & 15, ty = tid >> 4;
    int m0 = blockIdx.y * 64, n0 = blockIdx.x * 64;

    ull accp[4][2];
#pragma unroll
    for (int r = 0; r < 4; r++) { accp[r][0] = 0ull; accp[r][1] = 0ull; }

    int lr = tid >> 2;
    int lc = (tid & 3) * 4;
    const float* Ap = A + (size_t)(m0 + lr) * K + lc;
    bool wvalid = (n0 + lr) < Nn;
    const float* Wp = W + (size_t)(n0 + lr) * K + lc;

    for (int k0 = 0; k0 < K; k0 += 16) {
        float4 av = *(const float4*)(Ap + k0);
        float4 wv = wvalid ? *(const float4*)(Wp + k0) : make_float4(0.f, 0.f, 0.f, 0.f);
        __syncthreads();
        As[lc + 0][lr] = av.x; As[lc + 1][lr] = av.y;
        As[lc + 2][lr] = av.z; As[lc + 3][lr] = av.w;
        Ws[lc + 0][lr] = wv.x; Ws[lc + 1][lr] = wv.y;
        Ws[lc + 2][lr] = wv.z; Ws[lc + 3][lr] = wv.w;
        __syncthreads();
#pragma unroll
        for (int kk = 0; kk < 16; kk++) {
            float4 a4 = *(const float4*)&As[kk][ty * 4];
            const ull* bp = (const ull*)&Ws[kk][tx * 4];
            ull b0 = bp[0], b1 = bp[1];
            ull ax = dup2(a4.x), ay = dup2(a4.y), az = dup2(a4.z), aw = dup2(a4.w);
            ffma2(accp[0][0], ax, b0); ffma2(accp[0][1], ax, b1);
            ffma2(accp[1][0], ay, b0); ffma2(accp[1][1], ay, b1);
            ffma2(accp[2][0], az, b0); ffma2(accp[2][1], az, b1);
            ffma2(accp[3][0], aw, b0); ffma2(accp[3][1], aw, b1);
        }
    }
#pragma unroll
    for (int r = 0; r < 4; r++) {
        int m = m0 + ty * 4 + r;
        float cvals[4];
        float2 lo = *reinterpret_cast<float2*>(&accp[r][0]);
        float2 hi = *reinterpret_cast<float2*>(&accp[r][1]);
        cvals[0] = lo.x; cvals[1] = lo.y; cvals[2] = hi.x; cvals[3] = hi.y;
#pragma unroll
        for (int c = 0; c < 4; c++) {
            int n = n0 + tx * 4 + c;
            if (n < Nn) {
                float v = cvals[c] + (bias ? bias[n] : 0.f);
                if (relu) v = fmaxf(v, 0.f);
                C[(size_t)m * Nn + n] = v;
            }
        }
    }
}

// ---------------- HMMA GEMM for MLP layers (fp16 single-pass) --------------
// C[M x Nn] = act(A[M x K] @ W[Nn x K]^T + bias). Tiles 64x64, K staged by 64.
// SMEM layout per tile: [64 rows][32 words], word (r, w) at r*32 + (w ^ (4*(r&7))).
__global__ void __launch_bounds__(128) hgemm_kernel(
    const float* __restrict__ A, const float* __restrict__ W,
    const float* __restrict__ bias, float* __restrict__ C,
    int M, int Nn, int K, int relu)
{
    __shared__ __align__(16) char At[8192];
    __shared__ __align__(16) char Wt[8192];
    u32 smb_a = (u32)__cvta_generic_to_shared(At);
    u32 smb_w = (u32)__cvta_generic_to_shared(Wt);

    int tid = threadIdx.x;
    int m0 = blockIdx.y * 64, n0 = blockIdx.x * 64;

    int lane = tid & 31, warp = tid >> 5;     // warp owns rows warp*16..+16
    int gid = lane >> 2, tig = lane & 3;
    int r7 = lane & 7;
    int ak4 = ((lane >> 4) & 1) * 4;

    u32 aaddr[4], boffp[4];
    {
        int arow = warp * 16 + ((lane >> 3) & 1) * 8 + r7;
#pragma unroll
        for (int c = 0; c < 4; c++)
            aaddr[c] = smb_a + arow * 128 + (u32)(((8 * c + ak4) ^ (4 * r7)) * 4);
        int bk4 = ((lane >> 3) & 1) * 4;
        int bnb = ((lane >> 4) & 1) * 1024;
#pragma unroll
        for (int c = 0; c < 4; c++)
            boffp[c] = (u32)(bnb + r7 * 128 + ((8 * c + bk4) ^ (4 * r7)) * 4);
    }

    float acc[8][4];
#pragma unroll
    for (int nb = 0; nb < 8; nb++)
#pragma unroll
        for (int q = 0; q < 4; q++) acc[nb][q] = 0.f;

    for (int k0 = 0; k0 < K; k0 += 64) {
        __syncthreads();
        // stage A and W tiles (fp32 -> fp16, swizzled). 8 chunks each.
#pragma unroll
        for (int it = 0; it < 8; it++) {
            int idx = tid + it * 128;         // 0..1023
            int row = idx >> 4;               // 0..63
            int kf = idx & 15;                // k = kf*4 within stage
            int k = k0 + kf * 4;
            float4 av = (k < K) ? *(const float4*)(A + (size_t)(m0 + row) * K + k)
                                : make_float4(0.f, 0.f, 0.f, 0.f);
            bool wv_ok = (n0 + row) < Nn && k < K;
            float4 wv = wv_ok ? *(const float4*)(W + (size_t)(n0 + row) * K + k)
                              : make_float4(0.f, 0.f, 0.f, 0.f);
            __half2 a0 = __floats2half2_rn(av.x, av.y);
            __half2 a1 = __floats2half2_rn(av.z, av.w);
            __half2 w0 = __floats2half2_rn(wv.x, wv.y);
            __half2 w1 = __floats2half2_rn(wv.z, wv.w);
            u32 ws = (u32)((kf * 2) ^ (4 * (row & 7)));
            uint2 apk, wpk;
            apk.x = *reinterpret_cast<u32*>(&a0); apk.y = *reinterpret_cast<u32*>(&a1);
            wpk.x = *reinterpret_cast<u32*>(&w0); wpk.y = *reinterpret_cast<u32*>(&w1);
            *(uint2*)(At + row * 128 + ws * 4) = apk;
            *(uint2*)(Wt + row * 128 + ws * 4) = wpk;
        }
        __syncthreads();

#pragma unroll
        for (int c = 0; c < 4; c++) {
            u32 a0, a1, a2, a3;
            ldmx4(a0, a1, a2, a3, aaddr[c]);
#pragma unroll
            for (int np = 0; np < 4; np++) {
                u32 b00, b01, b10, b11;
                ldmx4(b00, b01, b10, b11, smb_w + boffp[c] + (u32)(np * 2048));
                mma16816h(acc[np * 2], a0, a1, a2, a3, b00, b01);
                mma16816h(acc[np * 2 + 1], a0, a1, a2, a3, b10, b11);
            }
        }
    }

    // epilogue: bias + relu, guarded store
    int mrow = m0 + warp * 16 + gid;
#pragma unroll
    for (int nb = 0; nb < 8; nb++) {
        int col = n0 + nb * 8 + tig * 2;
        if (col < Nn) {
            float b0 = bias ? bias[col] : 0.f;
            float b1 = bias ? bias[col + 1] : 0.f;
            float v0 = acc[nb][0] + b0, v1 = acc[nb][1] + b1;
            float v2 = acc[nb][2] + b0, v3 = acc[nb][3] + b1;
            if (relu) {
                v0 = fmaxf(v0, 0.f); v1 = fmaxf(v1, 0.f);
                v2 = fmaxf(v2, 0.f); v3 = fmaxf(v3, 0.f);
            }
            *(float2*)(C + (size_t)mrow * Nn + col) = make_float2(v0, v1);
            *(float2*)(C + (size_t)(mrow + 8) * Nn + col) = make_float2(v2, v3);
        }
    }
}

// --------- s/exp tables + per-tile swizzled fp16 B (one tau per block) ------
__global__ void __launch_bounds__(64) sab_kernel(const float* __restrict__ avec)
{
    extern __shared__ __align__(16) u32 st[];        // 2048 u32 = 8KB (one tau)
    int tid = threadIdx.x;                           // 0..63
    int j = blockIdx.x * 64 + tid;

    float v[DH];
    const float4* w4 = (const float4*)(g_Wh + (size_t)j * DH);
    float acc = 0.f;
#pragma unroll
    for (int q = 0; q < DH / 4; q++) {
        float4 wv = w4[q];
        float4 av = ((const float4*)avec)[q];
        v[q * 4 + 0] = wv.x; v[q * 4 + 1] = wv.y;
        v[q * 4 + 2] = wv.z; v[q * 4 + 3] = wv.w;
        acc += wv.x * av.x + wv.y * av.y + wv.z * av.z + wv.w * av.w;
    }
    g_s[j]  = acc;
    g_ea[j] = expf(acc);
    g_eb[j] = expf(0.2f * acc);

    int half = tid & 1, w = tid >> 1;
    __half* B = (__half*)st;
#pragma unroll
    for (int d = 0; d < DH; d++) {
        int widx = d * 32 + (w ^ (4 * (d & 7)));
        B[widx * 2 + half] = __float2half_rn(v[d]);
    }
    {
        int widx = 48 * 32 + w;                      // Z ones column (48&7==0)
        B[widx * 2 + half] = __float2half_rn(1.0f);
    }
#pragma unroll
    for (int d = 49; d < 64; d++) {
        int widx = d * 32 + (w ^ (4 * (d & 7)));
        B[widx * 2 + half] = __float2half_rn(0.0f);
    }
    __syncthreads();

    uint4* dst = (uint4*)(g_Bsw + (size_t)blockIdx.x * 2048);
    const uint4* src = (const uint4*)st;
#pragma unroll
    for (int it = 0; it < 8; it++)
        dst[tid + it * 64] = src[tid + it * 64];
}

// ------------------- HMMA attention (warp-specialized) ---------------------
// SMEM (bytes)
#define SM_ISL 0                    // si[128]@0 eai@512 ebi@1024
#define SM_JSL 1536                 // 2 stages x 768 (sj@0 eaj@256 ebj@512)
#define SM_A   4096                 // 2 stages x 16KB (128 rows x 128B swizzled fp16)
#define SM_B   36864                // 2 stages x 8KB
#define SM_TOTAL 53248

// barrier ids: 2/3 = ready(stage), 4/5 = consumed(stage), 6 = producer-local

__global__ void __launch_bounds__(256, 2) attn_hmma_kernel(const int* __restrict__ adj)
{
    extern __shared__ __align__(16) char sm[];
    u32 smb = (u32)__cvta_generic_to_shared(sm);
    int tid = threadIdx.x;
    int bx = blockIdx.x;
    int I0 = (bx >> 2) * 128;
    int jq = bx & 3;
    int tau0 = jq * TTILES;
    int jbase = jq * (NN / KSPLIT);

    if (tid >= 128) {
        // ========================= PRODUCER =========================
        int ptid = tid - 128;
        int c4 = (ptid & 15) << 2;       // fixed 4 j-columns
        int rbase = ptid >> 4;           // 0..7
        u32 wsbase = (u32)((c4 >> 1) ^ (4 * rbase));   // row&7 == rbase always

        // prologue copies: isl + B(0) + jsl(0)
        if (ptid < 96) {
            int table = ptid >> 5, idx = ptid & 31;
            const float* tp = (table == 0) ? g_s : (table == 1) ? g_ea : g_eb;
            cpa16(sm + SM_ISL + table * 512 + idx * 16, tp + I0 + idx * 4);
        }
        {
            const u32* src = g_Bsw + (size_t)tau0 * 2048;
#pragma unroll
            for (int k = 0; k < 4; k++) {
                int chunk = ptid + k * 128;
                cpa16(sm + SM_B + chunk * 16, src + chunk * 4);
            }
            if (ptid < 48) {
                int table = ptid >> 4, idx = ptid & 15;
                const float* tp = (table == 0) ? g_s : (table == 1) ? g_ea : g_eb;
                cpa16(sm + SM_JSL + table * 256 + idx * 16, tp + tau0 * 64 + idx * 4);
            }
        }
        cpa_commit();

        // adj prefetch tile 0
        int4 adjc[16];
#pragma unroll
        for (int p = 0; p < 16; p++)
            adjc[p] = *(const int4*)(adj + (size_t)(I0 + rbase + p * 8) * NN + jbase + c4);

        for (int t = 0; t < TTILES; t++) {
            int s = t & 1;
            if (t >= 2)
                bar_sync(4 + s, 256);    // A/B stage s consumed

            cpa_wait0();                 // B(t)/jsl(t)/(isl at t=0) landed
            bar_sync(6, 128);            // producer-local: copies visible

            const char* jsl = sm + SM_JSL + s * 768;
            float4 sjr = *(const float4*)(jsl + c4 * 4);
            float4 ear = *(const float4*)(jsl + 256 + c4 * 4);
            float4 ebr = *(const float4*)(jsl + 512 + c4 * 4);
            char* Ad = sm + SM_A + s * 16384;
            const float* isl0 = (const float*)(sm + SM_ISL);
#pragma unroll
            for (int p = 0; p < 16; p++) {
                int row = rbase + p * 8;
                float si  = isl0[row];
                float eai = isl0[128 + row];
                float ebi = isl0[256 + row];
                int4 a = adjc[p];
                float w0 = (si + sjr.x > 0.f) ? (eai * ear.x) : (ebi * ebr.x); if (!a.x) w0 = 0.f;
                float w1 = (si + sjr.y > 0.f) ? (eai * ear.y) : (ebi * ebr.y); if (!a.y) w1 = 0.f;
                float w2 = (si + sjr.z > 0.f) ? (eai * ear.z) : (ebi * ebr.z); if (!a.z) w2 = 0.f;
                float w3 = (si + sjr.w > 0.f) ? (eai * ear.w) : (ebi * ebr.w); if (!a.w) w3 = 0.f;
                __half2 hA = __floats2half2_rn(w0, w1);
                __half2 hB = __floats2half2_rn(w2, w3);
                uint2 hv;
                hv.x = *reinterpret_cast<u32*>(&hA);
                hv.y = *reinterpret_cast<u32*>(&hB);
                *(uint2*)(Ad + row * 128 + wsbase * 4) = hv;
            }
            asm volatile("membar.cta;" ::: "memory");
            bar_arrive(2 + s, 256);      // stage s ready

            if (t + 1 < TTILES) {
                const u32* src = g_Bsw + (size_t)(tau0 + t + 1) * 2048;
                char* Bst = sm + SM_B + (s ^ 1) * 8192;
#pragma unroll
                for (int k = 0; k < 4; k++) {
                    int chunk = ptid + k * 128;
                    cpa16(Bst + chunk * 16, src + chunk * 4);
                }
                if (ptid < 48) {
                    int table = ptid >> 4, idx = ptid & 15;
                    const float* tp = (table == 0) ? g_s : (table == 1) ? g_ea : g_eb;
                    cpa16(sm + SM_JSL + (s ^ 1) * 768 + table * 256 + idx * 16,
                          tp + (tau0 + t + 1) * 64 + idx * 4);
                }
                cpa_commit();
                int J = jbase + (t + 1) * 64;
#pragma unroll
                for (int p = 0; p < 16; p++)
                    adjc[p] = *(const int4*)(adj + (size_t)(I0 + rbase + p * 8) * NN + J + c4);
            }
        }
    } else {
        // ========================= CONSUMER =========================
        int lane = tid & 31, cw = tid >> 5;   // cw 0..3, owns rows [cw*32, cw*32+32)
        int gid = lane >> 2, tig = lane & 3;
        int r7 = lane & 7;
        int ak4 = ((lane >> 4) & 1) * 4;

        u32 aaddr[2][4];
#pragma unroll
        for (int m = 0; m < 2; m++) {
            int arow = cw * 32 + m * 16 + ((lane >> 3) & 1) * 8 + r7;
#pragma unroll
            for (int c = 0; c < 4; c++)
                aaddr[m][c] = smb + SM_A + arow * 128 + (u32)(((8 * c + ak4) ^ (4 * r7)) * 4);
        }
        u32 boffp[4];
        {
            int bk4 = ((lane >> 3) & 1) * 4;
            int bnb = ((lane >> 4) & 1) * 1024;
#pragma unroll
            for (int c = 0; c < 4; c++)
                boffp[c] = (u32)(bnb + r7 * 128 + ((8 * c + bk4) ^ (4 * r7)) * 4);
        }

        float acc[2][7][4];
#pragma unroll
        for (int m = 0; m < 2; m++)
#pragma unroll
            for (int nb = 0; nb < 7; nb++)
#pragma unroll
                for (int q = 0; q < 4; q++) acc[m][nb][q] = 0.f;

        for (int t = 0; t < TTILES; t++) {
            int s = t & 1;
            bar_sync(2 + s, 256);        // stage s ready
            u32 Aoff = (u32)(s * 16384);
            u32 Bst = smb + SM_B + (u32)(s * 8192);
#pragma unroll
            for (int c = 0; c < 4; c++) {
                u32 a00, a01, a02, a03, a10, a11, a12, a13;
                ldmx4(a00, a01, a02, a03, aaddr[0][c] + Aoff);
                ldmx4(a10, a11, a12, a13, aaddr[1][c] + Aoff);
#pragma unroll
                for (int np = 0; np < 4; np++) {
                    u32 b00, b01, b10, b11;
                    ldmx4(b00, b01, b10, b11, Bst + boffp[c] + (u32)(np * 2048));
                    mma16816h(acc[0][np * 2], a00, a01, a02, a03, b00, b01);
                    mma16816h(acc[1][np * 2], a10, a11, a12, a13, b00, b01);
                    if (np < 3) {
                        mma16816h(acc[0][np * 2 + 1], a00, a01, a02, a03, b10, b11);
                        mma16816h(acc[1][np * 2 + 1], a10, a11, a12, a13, b10, b11);
                    }
                }
            }
            bar_arrive(4 + s, 256);      // stage s consumed
        }

        // epilogue: write partials
#pragma unroll
        for (int m = 0; m < 2; m++) {
            float* dst = g_part + ((size_t)bx * 128 + cw * 32 + m * 16 + gid) * 64;
#pragma unroll
            for (int nb = 0; nb < 7; nb++) {
                int col = nb * 8 + tig * 2;
                *(float2*)(dst + col) = make_float2(acc[m][nb][0], acc[m][nb][1]);
                *(float2*)(dst + 8 * 64 + col) = make_float2(acc[m][nb][2], acc[m][nb][3]);
            }
        }
    }
}

// -------------------- reduce K-split + normalize + LayerNorm ----------------
__global__ void __launch_bounds__(256) reduce_ln_kernel(
    const float* __restrict__ gamma, const float* __restrict__ beta)
{
    int gt = blockIdx.x * 256 + threadIdx.x;     // 16384 threads
    int i = gt >> 1, half = gt & 1;
    int itile = i >> 7, r = i & 127;
    const float* p0 = g_part + ((size_t)(itile * 4 + 0) * 128 + r) * 64;
    const float* p1 = g_part + ((size_t)(itile * 4 + 1) * 128 + r) * 64;
    const float* p2 = g_part + ((size_t)(itile * 4 + 2) * 128 + r) * 64;
    const float* p3 = g_part + ((size_t)(itile * 4 + 3) * 128 + r) * 64;

    float4 v[6];
#pragma unroll
    for (int k = 0; k < 6; k++) {
        int q = half + 2 * k;
        float4 a = ((const float4*)p0)[q];
        float4 b = ((const float4*)p1)[q];
        float4 c = ((const float4*)p2)[q];
        float4 d = ((const float4*)p3)[q];
        v[k].x = (a.x + b.x) + (c.x + d.x);
        v[k].y = (a.y + b.y) + (c.y + d.y);
        v[k].z = (a.z + b.z) + (c.z + d.z);
        v[k].w = (a.w + b.w) + (c.w + d.w);
    }
    float Z = 0.f;
    if (half == 0)
        Z = (p0[48] + p1[48]) + (p2[48] + p3[48]);
    float Zo = __shfl_xor_sync(0xffffffffu, Z, 1);
    if (half == 1) Z = Zo;
    float rz = 1.0f / Z;

    float s1 = 0.f;
#pragma unroll
    for (int k = 0; k < 6; k++) {
        v[k].x *= rz; v[k].y *= rz; v[k].z *= rz; v[k].w *= rz;
        s1 += (v[k].x + v[k].y) + (v[k].z + v[k].w);
    }
    s1 += __shfl_xor_sync(0xffffffffu, s1, 1);
    float mu = s1 * (1.0f / DH);
    float s2 = 0.f;
#pragma unroll
    for (int k = 0; k < 6; k++) {
        float d0 = v[k].x - mu, d1 = v[k].y - mu, d2 = v[k].z - mu, d3 = v[k].w - mu;
        s2 += (d0 * d0 + d1 * d1) + (d2 * d2 + d3 * d3);
    }
    s2 += __shfl_xor_sync(0xffffffffu, s2, 1);
    float rstd = rsqrtf(s2 * (1.0f / DH) + 1e-5f);

    float* o = g_hn + (size_t)i * DH;
#pragma unroll
    for (int k = 0; k < 6; k++) {
        int q = half + 2 * k;
        float4 ov;
        ov.x = (v[k].x - mu) * rstd * gamma[q * 4 + 0] + beta[q * 4 + 0];
        ov.y = (v[k].y - mu) * rstd * gamma[q * 4 + 1] + beta[q * 4 + 1];
        ov.z = (v[k].z - mu) * rstd * gamma[q * 4 + 2] + beta[q * 4 + 2];
        ov.w = (v[k].w - mu) * rstd * gamma[q * 4 + 3] + beta[q * 4 + 3];
        *(float4*)(o + q * 4) = ov;
    }
}

// ------------------------- launch ------------------------------------------
extern "C" void kernel_launch(void* const* d_in, const int* in_sizes, int n_in,
                              void* d_out, int out_size)
{
    const float* x     = (const float*)d_in[0];
    const int*   adj   = (const int*)  d_in[1];
    const float* Wg    = (const float*)d_in[2];
    const float* avec  = (const float*)d_in[3];
    const float* gamma = (const float*)d_in[4];
    const float* beta  = (const float*)d_in[5];
    const float* W1    = (const float*)d_in[6];
    const float* b1    = (const float*)d_in[7];
    const float* W2    = (const float*)d_in[8];
    const float* b2    = (const float*)d_in[9];
    const float* W3    = (const float*)d_in[10];
    const float* b3    = (const float*)d_in[11];
    float* out = (float*)d_out;

    float *Wh, *hn, *m1, *m2;
    cudaGetSymbolAddress((void**)&Wh, g_Wh);
    cudaGetSymbolAddress((void**)&hn, g_hn);
    cudaGetSymbolAddress((void**)&m1, g_m1);
    cudaGetSymbolAddress((void**)&m2, g_m2);

    static int smem_set = 0;
    if (!smem_set) {
        cudaFuncSetAttribute(attn_hmma_kernel,
                             cudaFuncAttributeMaxDynamicSharedMemorySize, SM_TOTAL);
        cudaFuncSetAttribute(sab_kernel,
                             cudaFuncAttributeMaxDynamicSharedMemorySize, 8192);
        smem_set = 1;
    }

    // Wh = x @ W_gat^T   [8192 x 48]  (fp32 path: feeds exp tables)
    gemm_kernel<<<dim3(1, NN / 64), 256>>>(x, Wg, nullptr, Wh, NN, DH, DIN, 0);
    // s, exp tables, per-tile swizzled fp16 B (one tau per block, 128 CTAs)
    sab_kernel<<<128, 64, 8192>>>(avec);
    // warp-specialized HMMA attention -> g_part  (grid 256, 2 CTAs/SM)
    attn_hmma_kernel<<<NN / 128 * KSPLIT, 256, SM_TOTAL>>>(adj);
    // combine K-splits, normalize, LayerNorm -> g_hn
    reduce_ln_kernel<<<64, 256>>>(gamma, beta);
    // MLP head (fp16 HMMA)
    hgemm_kernel<<<dim3(DH1 / 64, NN / 64), 128>>>(hn, W1, b1, m1, NN, DH1, DH, 1);
    hgemm_kernel<<<dim3(DH2 / 64, NN / 64), 128>>>(m1, W2, b2, m2, NN, DH2, DH1, 1);
    hgemm_kernel<<<dim3(1, NN / 64), 128>>>(m2, W3, b3, out, NN, DOUT, DH2, 0);
}